// round 16
// baseline (speedup 1.0000x reference)
#include <cuda_runtime.h>
#include <cuda_bf16.h>
#include <cuda_fp16.h>
#include <math.h>
#include <stdint.h>

#define NN    100000
#define EE    1600000
#define HIDD  128
#define BB    512
#define LLAY  3
#define EPSV  1e-5f
#define NPART ((NN + 1023) / 1024)
#define NCHUNK 4
#define CHUNK  (NN / NCHUNK)

// ---------------- scratch (device globals; allocation-free) ----------------
__device__ __align__(16) __half g_x  [NN * HIDD];   // fp16 activations
__device__ __align__(16) __half g_xwA[NN * HIDD];   // fp16 xw ping (pre-scaled)
__device__ __align__(16) __half g_xwB[NN * HIDD];   // fp16 xw pong
__device__ __align__(16) __nv_bfloat16 g_wh[4 * HIDD * HIDD];
__device__ __align__(16) __nv_bfloat16 g_wl[4 * HIDD * HIDD];
__device__ __align__(16) float g_dinvs[NN];
__device__ __align__(16) float g_pool[BB * HIDD];
__device__ __align__(16) float g_cnt [BB];
// CSR
__device__ int   g_ecnt[NN];
__device__ int   g_cur [NN];
__device__ int   g_scan[NN];
__device__ int   g_rows[NN];
__device__ int   g_part [NPART];
__device__ int   g_partS[NPART];
__device__ int   g_csr_src[EE];

// ---------------- helpers ----------------
__device__ __forceinline__ void red_add_v4(float* p, float4 v) {
    asm volatile("red.global.add.v4.f32 [%0], {%1, %2, %3, %4};"
                 :: "l"(p), "f"(v.x), "f"(v.y), "f"(v.z), "f"(v.w)
                 : "memory");
}
__device__ __forceinline__ void stg_wt_v4(float* p, float4 v) {
    asm volatile("st.global.wt.v4.f32 [%0], {%1, %2, %3, %4};"
                 :: "l"(p), "f"(v.x), "f"(v.y), "f"(v.z), "f"(v.w)
                 : "memory");
}
__device__ __forceinline__ uint32_t smem_u32(const void* p) {
    uint32_t a;
    asm("{ .reg .u64 t; cvta.to.shared.u64 t, %1; cvt.u32.u64 %0, t; }"
        : "=r"(a) : "l"(p));
    return a;
}
__device__ __forceinline__ void cp16(uint32_t smaddr, const void* g) {
    asm volatile("cp.async.cg.shared.global [%0], [%1], 16;"
                 :: "r"(smaddr), "l"(g) : "memory");
}
__device__ __forceinline__ void cp_commit_wait() {
    asm volatile("cp.async.commit_group;" ::: "memory");
    asm volatile("cp.async.wait_group 0;" ::: "memory");
}
__device__ __forceinline__ void ldm_x4(uint32_t* r, uint32_t addr) {
    asm volatile("ldmatrix.sync.aligned.m8n8.x4.shared.b16 {%0,%1,%2,%3}, [%4];"
                 : "=r"(r[0]), "=r"(r[1]), "=r"(r[2]), "=r"(r[3]) : "r"(addr));
}
__device__ __forceinline__ void ldm_x4_t(uint32_t* r, uint32_t addr) {
    asm volatile("ldmatrix.sync.aligned.m8n8.x4.trans.shared.b16 {%0,%1,%2,%3}, [%4];"
                 : "=r"(r[0]), "=r"(r[1]), "=r"(r[2]), "=r"(r[3]) : "r"(addr));
}
__device__ __forceinline__ void mma_bf16(float* c, const uint32_t* a,
                                         uint32_t b0, uint32_t b1) {
    asm volatile(
        "mma.sync.aligned.m16n8k16.row.col.f32.bf16.bf16.f32 "
        "{%0,%1,%2,%3}, {%4,%5,%6,%7}, {%8,%9}, {%0,%1,%2,%3};"
        : "+f"(c[0]), "+f"(c[1]), "+f"(c[2]), "+f"(c[3])
        : "r"(a[0]), "r"(a[1]), "r"(a[2]), "r"(a[3]), "r"(b0), "r"(b1));
}
__device__ __forceinline__ float4 ld_h8(const uint2* p2, int s, int lane) {
    uint2 u = p2[s * 32 + lane];
    float2 a = __half22float2(*reinterpret_cast<__half2*>(&u.x));
    float2 b = __half22float2(*reinterpret_cast<__half2*>(&u.y));
    return make_float4(a.x, a.y, b.x, b.y);
}

// ---------------- init ----------------
__global__ void k_init() {
    int i = blockIdx.x * blockDim.x + threadIdx.x;
    if (i < NN)        { g_ecnt[i] = 0; g_cur[i] = 0; }
    if (i < BB * HIDD) g_pool[i] = 0.0f;
    if (i < BB)        g_cnt[i]  = 0.0f;
}

__global__ void k_wconv(const float* __restrict__ w_in,
                        const float* __restrict__ gcn_w) {
    int i = blockIdx.x * blockDim.x + threadIdx.x;
    if (i >= 4 * HIDD * HIDD) return;
    float v = (i < HIDD * HIDD) ? w_in[i] : gcn_w[i - HIDD * HIDD];
    __nv_bfloat16 h = __float2bfloat16(v);
    g_wh[i] = h;
    g_wl[i] = __float2bfloat16(v - __bfloat162float(h));
}

__global__ void k_deg(const int* __restrict__ dst) {
    int base = blockIdx.x * blockDim.x * 4 + threadIdx.x;
    int stride = blockDim.x;
    int d0 = -1, d1 = -1, d2 = -1, d3 = -1;
    if (base               < EE) d0 = dst[base];
    if (base +     stride  < EE) d1 = dst[base + stride];
    if (base + 2 * stride  < EE) d2 = dst[base + 2 * stride];
    if (base + 3 * stride  < EE) d3 = dst[base + 3 * stride];
    if (d0 >= 0) atomicAdd(&g_ecnt[d0], 1);
    if (d1 >= 0) atomicAdd(&g_ecnt[d1], 1);
    if (d2 >= 0) atomicAdd(&g_ecnt[d2], 1);
    if (d3 >= 0) atomicAdd(&g_ecnt[d3], 1);
}

// ---------------- scan / CSR build ----------------
__global__ void k_scan_blk() {
    __shared__ int sm[1024];
    int i = blockIdx.x * 1024 + threadIdx.x;
    int v = (i < NN) ? g_ecnt[i] : 0;
    sm[threadIdx.x] = v;
    __syncthreads();
    #pragma unroll
    for (int off = 1; off < 1024; off <<= 1) {
        int t = (threadIdx.x >= off) ? sm[threadIdx.x - off] : 0;
        __syncthreads();
        sm[threadIdx.x] += t;
        __syncthreads();
    }
    if (i < NN) g_scan[i] = sm[threadIdx.x];
    if (threadIdx.x == 1023) g_part[blockIdx.x] = sm[1023];
}

__global__ void k_scan_top() {
    if (threadIdx.x == 0) {
        int s = 0;
        for (int b = 0; b < NPART; b++) { s += g_part[b]; g_partS[b] = s; }
    }
}

__global__ void k_scan_fin() {
    int i = blockIdx.x * blockDim.x + threadIdx.x;
    if (i >= NN) return;
    int b = i >> 10;
    int cnt = g_ecnt[i];
    g_rows[i] = g_scan[i] - cnt + (b ? g_partS[b - 1] : 0);
    g_dinvs[i] = rsqrtf((float)cnt + 1.0f);
}

__global__ void k_fill(const int* __restrict__ src, const int* __restrict__ dst) {
    int e = blockIdx.x * blockDim.x + threadIdx.x;
    if (e >= EE) return;
    int d = dst[e];
    int slot = g_rows[d] + atomicAdd(&g_cur[d], 1);
    g_csr_src[slot] = src[e];
}

// ======== GEMM: rows [rbase_n, mend) @ [128,128], 3-pass split-bf16 =========
// mode 0: g_x         = fp16(X @ W + bias)        (X = fp32 nodes)
// mode 1: xw(obuf)    = fp16((g_x @ W) * dinvs)   (A = fp16 g_x)
#define GSTRIDE 272
#define ATILE   (64 * GSTRIDE)
#define WTILE   (128 * GSTRIDE)
#define OFF_AHI 0
#define OFF_ALO (ATILE)
#define OFF_WHI (2 * ATILE)
#define OFF_WLO (2 * ATILE + WTILE)
#define GSMEM   (2 * ATILE + 2 * WTILE)  // 104448 B

__global__ void __launch_bounds__(256, 2)
k_gemm_mma(const float* __restrict__ Xext,
           const float* __restrict__ bias,
           int rbase_n, int mend, int mode, int wslot, int obuf)
{
    extern __shared__ char smem[];
    const uint32_t smb = smem_u32(smem);
    const int tid  = threadIdx.x;
    const int row0 = rbase_n + blockIdx.x * 64;

    const __nv_bfloat16* Wh = g_wh + wslot * HIDD * HIDD;
    const __nv_bfloat16* Wl = g_wl + wslot * HIDD * HIDD;

    #pragma unroll
    for (int t = 0; t < 8; t++) {
        int idx = tid + 256 * t;
        int row = idx >> 4;
        int c   = idx & 15;
        uint32_t so = row * GSTRIDE + c * 16;
        int ge = row * 128 + c * 8;
        cp16(smb + OFF_WHI + so, Wh + ge);
        cp16(smb + OFF_WLO + so, Wl + ge);
    }

    // ---- A tile: 64 rows x 128 k, bf16 hi/lo split ----
    #pragma unroll
    for (int i = 0; i < 16; i++) {
        int idx = tid + 256 * i;
        int row = idx >> 6;
        int kp  = idx & 63;           // unit of 2 k-values
        int gr  = row0 + row;
        float2 v;
        if (gr < mend) {
            if (mode == 0) {
                v = reinterpret_cast<const float2*>(Xext)[gr * 64 + kp];
            } else {
                uint32_t u = reinterpret_cast<const uint32_t*>(g_x)[gr * 64 + kp];
                v = __half22float2(*reinterpret_cast<__half2*>(&u));
            }
        } else v = make_float2(0.f, 0.f);
        __nv_bfloat162 h2 = __float22bfloat162_rn(v);
        float2 hf = __bfloat1622float2(h2);
        __nv_bfloat162 l2 = __float22bfloat162_rn(
                               make_float2(v.x - hf.x, v.y - hf.y));
        int off = row * GSTRIDE + kp * 4;
        *reinterpret_cast<uint32_t*>(smem + OFF_AHI + off) =
            *reinterpret_cast<uint32_t*>(&h2);
        *reinterpret_cast<uint32_t*>(smem + OFF_ALO + off) =
            *reinterpret_cast<uint32_t*>(&l2);
    }
    cp_commit_wait();
    __syncthreads();

    const int wid  = tid >> 5;
    const int lane = tid & 31;
    const int mb   = (wid >> 1) * 16;
    const int nb   = (wid & 1) * 64;

    const int a_r  = lane & 15;
    const int a_kb = (lane >> 4) << 4;
    const int b_r  = lane & 7;
    const int b_kh = ((lane >> 3) & 1) << 3;
    const int b_nh = ((lane >> 4) & 1) << 3;

    float acc[8][4];
    #pragma unroll
    for (int nt = 0; nt < 8; nt++)
        #pragma unroll
        for (int q = 0; q < 4; q++) acc[nt][q] = 0.f;

    const uint32_t passA[3] = {OFF_AHI, OFF_AHI, OFF_ALO};
    const uint32_t passB[3] = {OFF_WHI, OFF_WLO, OFF_WHI};

    #pragma unroll
    for (int p = 0; p < 3; p++) {
        uint32_t Ab = smb + passA[p];
        uint32_t Bb = smb + passB[p];
        #pragma unroll
        for (int ks = 0; ks < 8; ks++) {
            uint32_t a[4];
            ldm_x4(a, Ab + (mb + a_r) * GSTRIDE + ks * 32 + a_kb);
            #pragma unroll
            for (int np = 0; np < 4; np++) {
                uint32_t b[4];
                ldm_x4_t(b, Bb + (ks * 16 + b_kh + b_r) * GSTRIDE
                             + (nb + np * 16 + b_nh) * 2);
                mma_bf16(acc[np*2],   a, b[0], b[1]);
                mma_bf16(acc[np*2+1], a, b[2], b[3]);
            }
        }
    }

    // ---- epilogue (fp16 outputs) ----
    const int tq = lane >> 2;
    const int tr = (lane & 3) * 2;
    int rbase = row0 + mb + tq;
    if (mode == 0) {
        #pragma unroll
        for (int nt = 0; nt < 8; nt++) {
            int col = nb + nt * 8 + tr;
            float2 bv = *reinterpret_cast<const float2*>(&bias[col]);
            __half2 h0 = __floats2half2_rn(acc[nt][0] + bv.x, acc[nt][1] + bv.y);
            __half2 h1 = __floats2half2_rn(acc[nt][2] + bv.x, acc[nt][3] + bv.y);
            if (rbase < mend)
                *reinterpret_cast<__half2*>(&g_x[rbase * 128 + col]) = h0;
            if (rbase + 8 < mend)
                *reinterpret_cast<__half2*>(&g_x[(rbase + 8) * 128 + col]) = h1;
        }
    } else {
        __half* xw = obuf ? g_xwB : g_xwA;
        float s0 = (rbase < mend)     ? g_dinvs[rbase]     : 1.f;
        float s1 = (rbase + 8 < mend) ? g_dinvs[rbase + 8] : 1.f;
        #pragma unroll
        for (int nt = 0; nt < 8; nt++) {
            int col = nb + nt * 8 + tr;
            __half2 h0 = __floats2half2_rn(acc[nt][0] * s0, acc[nt][1] * s0);
            __half2 h1 = __floats2half2_rn(acc[nt][2] * s1, acc[nt][3] * s1);
            if (rbase < mend)
                *reinterpret_cast<__half2*>(&xw[rbase * 128 + col]) = h0;
            if (rbase + 8 < mend)
                *reinterpret_cast<__half2*>(&xw[(rbase + 8) * 128 + col]) = h1;
        }
    }
}

// ------- fused: fp16 gather-sum + scale + bias + LN + ReLU + res (+pool) ----
__global__ void k_aggln(const float* __restrict__ bias,
                        const float* __restrict__ gamma,
                        const float* __restrict__ beta,
                        float* __restrict__ dout,
                        const int* __restrict__ batch_idx,
                        int n0, int ncount, int ibuf,
                        int add_res, int write_out)
{
    int t = blockIdx.x * blockDim.x + threadIdx.x;
    int nl   = t >> 5;
    int lane = t & 31;
    if (nl >= ncount) return;
    int n = n0 + nl;

    const uint2* xw2 = reinterpret_cast<const uint2*>(ibuf ? g_xwB : g_xwA);

    float4 acc = ld_h8(xw2, n, lane);   // self term (pre-scaled)

    int beg = g_rows[n];
    int end = beg + g_ecnt[n];
    int k = beg;
    for (; k + 4 <= end; k += 4) {
        int s0 = g_csr_src[k],   s1 = g_csr_src[k+1];
        int s2 = g_csr_src[k+2], s3 = g_csr_src[k+3];
        float4 v0 = ld_h8(xw2, s0, lane);
        float4 v1 = ld_h8(xw2, s1, lane);
        float4 v2 = ld_h8(xw2, s2, lane);
        float4 v3 = ld_h8(xw2, s3, lane);
        acc.x += (v0.x + v1.x) + (v2.x + v3.x);
        acc.y += (v0.y + v1.y) + (v2.y + v3.y);
        acc.z += (v0.z + v1.z) + (v2.z + v3.z);
        acc.w += (v0.w + v1.w) + (v2.w + v3.w);
    }
    for (; k < end; k++) {
        float4 v = ld_h8(xw2, g_csr_src[k], lane);
        acc.x += v.x; acc.y += v.y; acc.z += v.z; acc.w += v.w;
    }

    float dn = g_dinvs[n];
    float4 bv = reinterpret_cast<const float4*>(bias)[lane];
    acc.x = fmaf(acc.x, dn, bv.x);
    acc.y = fmaf(acc.y, dn, bv.y);
    acc.z = fmaf(acc.z, dn, bv.z);
    acc.w = fmaf(acc.w, dn, bv.w);

    float s = acc.x + acc.y + acc.z + acc.w;
    float q = acc.x*acc.x + acc.y*acc.y + acc.z*acc.z + acc.w*acc.w;
    #pragma unroll
    for (int o = 16; o; o >>= 1) {
        s += __shfl_xor_sync(0xffffffffu, s, o);
        q += __shfl_xor_sync(0xffffffffu, q, o);
    }
    float mu  = s * (1.0f / 128.0f);
    float var = q * (1.0f / 128.0f) - mu * mu;
    float rs  = rsqrtf(var + EPSV);

    float4 gg = reinterpret_cast<const float4*>(gamma)[lane];
    float4 bt = reinterpret_cast<const float4*>(beta)[lane];
    float4 y;
    y.x = fmaxf(fmaf((acc.x - mu) * rs, gg.x, bt.x), 0.f);
    y.y = fmaxf(fmaf((acc.y - mu) * rs, gg.y, bt.y), 0.f);
    y.z = fmaxf(fmaf((acc.z - mu) * rs, gg.z, bt.z), 0.f);
    y.w = fmaxf(fmaf((acc.w - mu) * rs, gg.w, bt.w), 0.f);

    if (add_res) {
        float4 r = ld_h8(reinterpret_cast<const uint2*>(g_x), n, lane);
        y.x += r.x; y.y += r.y; y.z += r.z; y.w += r.w;
    }

    if (write_out) {
        stg_wt_v4(&dout[n * 128 + lane * 4], y);
        int b = batch_idx[n];
        red_add_v4(&g_pool[b * 128 + lane * 4], y);
        if (lane == 0) atomicAdd(&g_cnt[b], 1.0f);
    } else {
        uint2 u;
        __half2 h0 = __floats2half2_rn(y.x, y.y);
        __half2 h1 = __floats2half2_rn(y.z, y.w);
        u.x = *reinterpret_cast<uint32_t*>(&h0);
        u.y = *reinterpret_cast<uint32_t*>(&h1);
        reinterpret_cast<uint2*>(g_x)[n * 32 + lane] = u;
    }
}

__global__ void k_poolfin(float* __restrict__ dout) {
    int i = blockIdx.x * blockDim.x + threadIdx.x;
    if (i >= BB * HIDD) return;
    int b = i >> 7;
    float v = g_pool[i] / fmaxf(g_cnt[b], 1.0f);
    asm volatile("st.global.wt.f32 [%0], %1;"
                 :: "l"(&dout[NN * HIDD + i]), "f"(v) : "memory");
}

// ---------------- launch ------------------------------------------------------
extern "C" void kernel_launch(void* const* d_in, const int* in_sizes, int n_in,
                              void* d_out, int out_size)
{
    const float* nodes     = (const float*)d_in[0];
    const int*   edges     = (const int*)  d_in[1];
    const int*   batch_idx = (const int*)  d_in[3];
    const float* w_in      = (const float*)d_in[4];
    const float* b_in      = (const float*)d_in[5];
    const float* gcn_w     = (const float*)d_in[6];
    const float* gcn_b     = (const float*)d_in[7];
    const float* ln_g      = (const float*)d_in[8];
    const float* ln_b      = (const float*)d_in[9];
    float*       out       = (float*)d_out;

    const int* src = edges;
    const int* dst = edges + EE;

    static cudaStream_t s2 = nullptr;
    static cudaEvent_t ev_fork = nullptr, ev_mid = nullptr, ev_join = nullptr;
    static cudaEvent_t ev_a[2][NCHUNK];
    static cudaEvent_t ev_g[2];
    static bool attr_set = false;
    if (!attr_set) {
        cudaFuncSetAttribute(k_gemm_mma,
                             cudaFuncAttributeMaxDynamicSharedMemorySize, GSMEM);
        cudaStreamCreateWithFlags(&s2, cudaStreamNonBlocking);
        cudaEventCreateWithFlags(&ev_fork, cudaEventDisableTiming);
        cudaEventCreateWithFlags(&ev_mid,  cudaEventDisableTiming);
        cudaEventCreateWithFlags(&ev_join, cudaEventDisableTiming);
        for (int i = 0; i < 2; i++) {
            cudaEventCreateWithFlags(&ev_g[i], cudaEventDisableTiming);
            for (int c = 0; c < NCHUNK; c++)
                cudaEventCreateWithFlags(&ev_a[i][c], cudaEventDisableTiming);
        }
        attr_set = true;
    }

    const int T = 256;
    const int INIT_N = (NN > BB * HIDD) ? NN : (BB * HIDD);
    const int FULL_GRID  = (NN + 63) / 64;
    const int CHUNK_GRID = (CHUNK + 63) / 64;
    const int AGG_GRID   = (CHUNK * 32 + T - 1) / T;

    // fork: side stream does wconv + input-projection GEMM
    cudaEventRecord(ev_fork, 0);
    cudaStreamWaitEvent(s2, ev_fork, 0);
    k_wconv<<<(4 * HIDD * HIDD + T - 1) / T, T, 0, s2>>>(w_in, gcn_w);
    k_gemm_mma<<<FULL_GRID, T, GSMEM, s2>>>(nodes, b_in, 0, NN, 0, 0, 0);

    // main stream: CSR prep up through scan_fin
    k_init <<<(INIT_N + T - 1) / T, T>>>();
    k_deg  <<<(EE + T * 4 - 1) / (T * 4), T>>>(dst);
    k_scan_blk<<<NPART, 1024>>>();
    k_scan_top<<<1, 32>>>();
    k_scan_fin<<<(NN + T - 1) / T, T>>>();
    cudaEventRecord(ev_mid, 0);

    // side stream: layer-0 GEMM (writes xw buf 0) overlaps k_fill
    cudaStreamWaitEvent(s2, ev_mid, 0);
    k_gemm_mma<<<FULL_GRID, T, GSMEM, s2>>>(nullptr, nullptr, 0, NN, 1, 1, 0);
    cudaEventRecord(ev_join, s2);

    k_fill<<<(EE + T - 1) / T, T>>>(src, dst);
    cudaStreamWaitEvent(0, ev_join, 0);

    // ---- layer loop: aggln(i) reads buf i%2; GEMM(i+1) writes buf (i+1)%2 ----
    for (int i = 0; i < LLAY; i++) {
        int add_res   = (i > 0) ? 1 : 0;
        int write_out = (i == LLAY - 1) ? 1 : 0;
        int ibuf = i & 1;
        if (i < LLAY - 1) {
            int obuf = (i + 1) & 1;
            for (int c = 0; c < NCHUNK; c++) {
                int n0 = c * CHUNK;
                k_aggln<<<AGG_GRID, T>>>(gcn_b + i * HIDD,
                                         ln_g + i * HIDD, ln_b + i * HIDD,
                                         out, batch_idx, n0, CHUNK, ibuf,
                                         add_res, write_out);
                cudaEventRecord(ev_a[i][c], 0);
                cudaStreamWaitEvent(s2, ev_a[i][c], 0);
                k_gemm_mma<<<CHUNK_GRID, T, GSMEM, s2>>>(
                    nullptr, nullptr, n0, n0 + CHUNK, 1, i + 2, obuf);
            }
            cudaEventRecord(ev_g[i], s2);
            cudaStreamWaitEvent(0, ev_g[i], 0);
        } else {
            k_aggln<<<(NN * 32 + T - 1) / T, T>>>(gcn_b + i * HIDD,
                                                  ln_g + i * HIDD,
                                                  ln_b + i * HIDD,
                                                  out, batch_idx, 0, NN, ibuf,
                                                  add_res, write_out);
        }
    }

    k_poolfin<<<(BB * HIDD + T - 1) / T, T>>>(out);
}

// round 17
// speedup vs baseline: 1.1505x; 1.1505x over previous
#include <cuda_runtime.h>
#include <cuda_bf16.h>
#include <cuda_fp16.h>
#include <math.h>
#include <stdint.h>

#define NN    100000
#define EE    1600000
#define HIDD  128
#define BB    512
#define LLAY  3
#define EPSV  1e-5f
#define NPART ((NN + 1023) / 1024)

// ---------------- scratch (device globals; allocation-free) ----------------
__device__ __align__(16) __half g_x  [NN * HIDD];   // fp16 activations
__device__ __align__(16) __half g_xw [NN * HIDD];   // fp16 xw (pre-scaled)
__device__ __align__(16) __nv_bfloat16 g_wh[4 * HIDD * HIDD];
__device__ __align__(16) __nv_bfloat16 g_wl[4 * HIDD * HIDD];
__device__ __align__(16) float g_dinvs[NN];
__device__ __align__(16) float g_pool[BB * HIDD];
__device__ __align__(16) float g_cnt [BB];
// CSR
__device__ int   g_ecnt[NN];
__device__ int   g_cur [NN];
__device__ int   g_scan[NN];
__device__ int   g_rows[NN];
__device__ int   g_part [NPART];
__device__ int   g_partS[NPART];
__device__ int   g_csr_src[EE];

// ---------------- helpers ----------------
__device__ __forceinline__ void red_add_v4(float* p, float4 v) {
    asm volatile("red.global.add.v4.f32 [%0], {%1, %2, %3, %4};"
                 :: "l"(p), "f"(v.x), "f"(v.y), "f"(v.z), "f"(v.w)
                 : "memory");
}
__device__ __forceinline__ void stg_wt_v4(float* p, float4 v) {
    asm volatile("st.global.wt.v4.f32 [%0], {%1, %2, %3, %4};"
                 :: "l"(p), "f"(v.x), "f"(v.y), "f"(v.z), "f"(v.w)
                 : "memory");
}
__device__ __forceinline__ uint32_t smem_u32(const void* p) {
    uint32_t a;
    asm("{ .reg .u64 t; cvta.to.shared.u64 t, %1; cvt.u32.u64 %0, t; }"
        : "=r"(a) : "l"(p));
    return a;
}
__device__ __forceinline__ void cp16(uint32_t smaddr, const void* g) {
    asm volatile("cp.async.cg.shared.global [%0], [%1], 16;"
                 :: "r"(smaddr), "l"(g) : "memory");
}
__device__ __forceinline__ void cp_commit_wait() {
    asm volatile("cp.async.commit_group;" ::: "memory");
    asm volatile("cp.async.wait_group 0;" ::: "memory");
}
__device__ __forceinline__ void ldm_x4(uint32_t* r, uint32_t addr) {
    asm volatile("ldmatrix.sync.aligned.m8n8.x4.shared.b16 {%0,%1,%2,%3}, [%4];"
                 : "=r"(r[0]), "=r"(r[1]), "=r"(r[2]), "=r"(r[3]) : "r"(addr));
}
__device__ __forceinline__ void ldm_x4_t(uint32_t* r, uint32_t addr) {
    asm volatile("ldmatrix.sync.aligned.m8n8.x4.trans.shared.b16 {%0,%1,%2,%3}, [%4];"
                 : "=r"(r[0]), "=r"(r[1]), "=r"(r[2]), "=r"(r[3]) : "r"(addr));
}
__device__ __forceinline__ void mma_bf16(float* c, const uint32_t* a,
                                         uint32_t b0, uint32_t b1) {
    asm volatile(
        "mma.sync.aligned.m16n8k16.row.col.f32.bf16.bf16.f32 "
        "{%0,%1,%2,%3}, {%4,%5,%6,%7}, {%8,%9}, {%0,%1,%2,%3};"
        : "+f"(c[0]), "+f"(c[1]), "+f"(c[2]), "+f"(c[3])
        : "r"(a[0]), "r"(a[1]), "r"(a[2]), "r"(a[3]), "r"(b0), "r"(b1));
}
__device__ __forceinline__ float4 ld_h8(const uint2* p2, int s, int lane) {
    uint2 u = p2[s * 32 + lane];
    float2 a = __half22float2(*reinterpret_cast<__half2*>(&u.x));
    float2 b = __half22float2(*reinterpret_cast<__half2*>(&u.y));
    return make_float4(a.x, a.y, b.x, b.y);
}

// ---------------- init ----------------
__global__ void k_init() {
    int i = blockIdx.x * blockDim.x + threadIdx.x;
    if (i < NN)        { g_ecnt[i] = 0; g_cur[i] = 0; }
    if (i < BB * HIDD) g_pool[i] = 0.0f;
    if (i < BB)        g_cnt[i]  = 0.0f;
}

__global__ void k_wconv(const float* __restrict__ w_in,
                        const float* __restrict__ gcn_w) {
    int i = blockIdx.x * blockDim.x + threadIdx.x;
    if (i >= 4 * HIDD * HIDD) return;
    float v = (i < HIDD * HIDD) ? w_in[i] : gcn_w[i - HIDD * HIDD];
    __nv_bfloat16 h = __float2bfloat16(v);
    g_wh[i] = h;
    g_wl[i] = __float2bfloat16(v - __bfloat162float(h));
}

__global__ void k_deg(const int* __restrict__ dst) {
    int base = blockIdx.x * blockDim.x * 4 + threadIdx.x;
    int stride = blockDim.x;
    int d0 = -1, d1 = -1, d2 = -1, d3 = -1;
    if (base               < EE) d0 = dst[base];
    if (base +     stride  < EE) d1 = dst[base + stride];
    if (base + 2 * stride  < EE) d2 = dst[base + 2 * stride];
    if (base + 3 * stride  < EE) d3 = dst[base + 3 * stride];
    if (d0 >= 0) atomicAdd(&g_ecnt[d0], 1);
    if (d1 >= 0) atomicAdd(&g_ecnt[d1], 1);
    if (d2 >= 0) atomicAdd(&g_ecnt[d2], 1);
    if (d3 >= 0) atomicAdd(&g_ecnt[d3], 1);
}

// ---------------- scan / CSR build ----------------
__global__ void k_scan_blk() {
    __shared__ int sm[1024];
    int i = blockIdx.x * 1024 + threadIdx.x;
    int v = (i < NN) ? g_ecnt[i] : 0;
    sm[threadIdx.x] = v;
    __syncthreads();
    #pragma unroll
    for (int off = 1; off < 1024; off <<= 1) {
        int t = (threadIdx.x >= off) ? sm[threadIdx.x - off] : 0;
        __syncthreads();
        sm[threadIdx.x] += t;
        __syncthreads();
    }
    if (i < NN) g_scan[i] = sm[threadIdx.x];
    if (threadIdx.x == 1023) g_part[blockIdx.x] = sm[1023];
}

__global__ void k_scan_top() {
    if (threadIdx.x == 0) {
        int s = 0;
        for (int b = 0; b < NPART; b++) { s += g_part[b]; g_partS[b] = s; }
    }
}

__global__ void k_scan_fin() {
    int i = blockIdx.x * blockDim.x + threadIdx.x;
    if (i >= NN) return;
    int b = i >> 10;
    int cnt = g_ecnt[i];
    g_rows[i] = g_scan[i] - cnt + (b ? g_partS[b - 1] : 0);
    g_dinvs[i] = rsqrtf((float)cnt + 1.0f);
}

__global__ void k_fill(const int* __restrict__ src, const int* __restrict__ dst) {
    int e = blockIdx.x * blockDim.x + threadIdx.x;
    if (e >= EE) return;
    int d = dst[e];
    int slot = g_rows[d] + atomicAdd(&g_cur[d], 1);
    g_csr_src[slot] = src[e];
}

// ======== GEMM: rows [rbase_n, mend) @ [128,128], 3-pass split-bf16 =========
// mode 0: g_x  = fp16(X @ W + bias)        (X = fp32 nodes)
// mode 1: g_xw = fp16((g_x @ W) * dinvs)   (A = fp16 g_x)
#define GSTRIDE 272
#define ATILE   (64 * GSTRIDE)
#define WTILE   (128 * GSTRIDE)
#define OFF_AHI 0
#define OFF_ALO (ATILE)
#define OFF_WHI (2 * ATILE)
#define OFF_WLO (2 * ATILE + WTILE)
#define GSMEM   (2 * ATILE + 2 * WTILE)  // 104448 B

__global__ void __launch_bounds__(256, 2)
k_gemm_mma(const float* __restrict__ Xext,
           const float* __restrict__ bias,
           int rbase_n, int mend, int mode, int wslot)
{
    extern __shared__ char smem[];
    const uint32_t smb = smem_u32(smem);
    const int tid  = threadIdx.x;
    const int row0 = rbase_n + blockIdx.x * 64;

    const __nv_bfloat16* Wh = g_wh + wslot * HIDD * HIDD;
    const __nv_bfloat16* Wl = g_wl + wslot * HIDD * HIDD;

    #pragma unroll
    for (int t = 0; t < 8; t++) {
        int idx = tid + 256 * t;
        int row = idx >> 4;
        int c   = idx & 15;
        uint32_t so = row * GSTRIDE + c * 16;
        int ge = row * 128 + c * 8;
        cp16(smb + OFF_WHI + so, Wh + ge);
        cp16(smb + OFF_WLO + so, Wl + ge);
    }

    // ---- A tile: 64 rows x 128 k, bf16 hi/lo split ----
    #pragma unroll
    for (int i = 0; i < 16; i++) {
        int idx = tid + 256 * i;
        int row = idx >> 6;
        int kp  = idx & 63;           // unit of 2 k-values
        int gr  = row0 + row;
        float2 v;
        if (gr < mend) {
            if (mode == 0) {
                v = reinterpret_cast<const float2*>(Xext)[gr * 64 + kp];
            } else {
                uint32_t u = reinterpret_cast<const uint32_t*>(g_x)[gr * 64 + kp];
                v = __half22float2(*reinterpret_cast<__half2*>(&u));
            }
        } else v = make_float2(0.f, 0.f);
        __nv_bfloat162 h2 = __float22bfloat162_rn(v);
        float2 hf = __bfloat1622float2(h2);
        __nv_bfloat162 l2 = __float22bfloat162_rn(
                               make_float2(v.x - hf.x, v.y - hf.y));
        int off = row * GSTRIDE + kp * 4;
        *reinterpret_cast<uint32_t*>(smem + OFF_AHI + off) =
            *reinterpret_cast<uint32_t*>(&h2);
        *reinterpret_cast<uint32_t*>(smem + OFF_ALO + off) =
            *reinterpret_cast<uint32_t*>(&l2);
    }
    cp_commit_wait();
    __syncthreads();

    const int wid  = tid >> 5;
    const int lane = tid & 31;
    const int mb   = (wid >> 1) * 16;
    const int nb   = (wid & 1) * 64;

    const int a_r  = lane & 15;
    const int a_kb = (lane >> 4) << 4;
    const int b_r  = lane & 7;
    const int b_kh = ((lane >> 3) & 1) << 3;
    const int b_nh = ((lane >> 4) & 1) << 3;

    float acc[8][4];
    #pragma unroll
    for (int nt = 0; nt < 8; nt++)
        #pragma unroll
        for (int q = 0; q < 4; q++) acc[nt][q] = 0.f;

    const uint32_t passA[3] = {OFF_AHI, OFF_AHI, OFF_ALO};
    const uint32_t passB[3] = {OFF_WHI, OFF_WLO, OFF_WHI};

    #pragma unroll
    for (int p = 0; p < 3; p++) {
        uint32_t Ab = smb + passA[p];
        uint32_t Bb = smb + passB[p];
        #pragma unroll
        for (int ks = 0; ks < 8; ks++) {
            uint32_t a[4];
            ldm_x4(a, Ab + (mb + a_r) * GSTRIDE + ks * 32 + a_kb);
            #pragma unroll
            for (int np = 0; np < 4; np++) {
                uint32_t b[4];
                ldm_x4_t(b, Bb + (ks * 16 + b_kh + b_r) * GSTRIDE
                             + (nb + np * 16 + b_nh) * 2);
                mma_bf16(acc[np*2],   a, b[0], b[1]);
                mma_bf16(acc[np*2+1], a, b[2], b[3]);
            }
        }
    }

    // ---- epilogue (fp16 outputs) ----
    const int tq = lane >> 2;
    const int tr = (lane & 3) * 2;
    int rbase = row0 + mb + tq;
    if (mode == 0) {
        #pragma unroll
        for (int nt = 0; nt < 8; nt++) {
            int col = nb + nt * 8 + tr;
            float2 bv = *reinterpret_cast<const float2*>(&bias[col]);
            __half2 h0 = __floats2half2_rn(acc[nt][0] + bv.x, acc[nt][1] + bv.y);
            __half2 h1 = __floats2half2_rn(acc[nt][2] + bv.x, acc[nt][3] + bv.y);
            if (rbase < mend)
                *reinterpret_cast<__half2*>(&g_x[rbase * 128 + col]) = h0;
            if (rbase + 8 < mend)
                *reinterpret_cast<__half2*>(&g_x[(rbase + 8) * 128 + col]) = h1;
        }
    } else {
        float s0 = (rbase < mend)     ? g_dinvs[rbase]     : 1.f;
        float s1 = (rbase + 8 < mend) ? g_dinvs[rbase + 8] : 1.f;
        #pragma unroll
        for (int nt = 0; nt < 8; nt++) {
            int col = nb + nt * 8 + tr;
            __half2 h0 = __floats2half2_rn(acc[nt][0] * s0, acc[nt][1] * s0);
            __half2 h1 = __floats2half2_rn(acc[nt][2] * s1, acc[nt][3] * s1);
            if (rbase < mend)
                *reinterpret_cast<__half2*>(&g_xw[rbase * 128 + col]) = h0;
            if (rbase + 8 < mend)
                *reinterpret_cast<__half2*>(&g_xw[(rbase + 8) * 128 + col]) = h1;
        }
    }
}

// ------- fused: fp16 gather-sum + scale + bias + LN + ReLU + res (+pool) ----
__global__ void k_aggln(const float* __restrict__ bias,
                        const float* __restrict__ gamma,
                        const float* __restrict__ beta,
                        float* __restrict__ dout,
                        const int* __restrict__ batch_idx,
                        int add_res, int write_out)
{
    int t = blockIdx.x * blockDim.x + threadIdx.x;
    int n    = t >> 5;
    int lane = t & 31;
    if (n >= NN) return;

    const uint2* xw2 = reinterpret_cast<const uint2*>(g_xw);

    float4 acc = ld_h8(xw2, n, lane);   // self term (pre-scaled)

    int beg = g_rows[n];
    int end = beg + g_ecnt[n];
    int k = beg;
    for (; k + 4 <= end; k += 4) {
        int s0 = g_csr_src[k],   s1 = g_csr_src[k+1];
        int s2 = g_csr_src[k+2], s3 = g_csr_src[k+3];
        float4 v0 = ld_h8(xw2, s0, lane);
        float4 v1 = ld_h8(xw2, s1, lane);
        float4 v2 = ld_h8(xw2, s2, lane);
        float4 v3 = ld_h8(xw2, s3, lane);
        acc.x += (v0.x + v1.x) + (v2.x + v3.x);
        acc.y += (v0.y + v1.y) + (v2.y + v3.y);
        acc.z += (v0.z + v1.z) + (v2.z + v3.z);
        acc.w += (v0.w + v1.w) + (v2.w + v3.w);
    }
    for (; k < end; k++) {
        float4 v = ld_h8(xw2, g_csr_src[k], lane);
        acc.x += v.x; acc.y += v.y; acc.z += v.z; acc.w += v.w;
    }

    float dn = g_dinvs[n];
    float4 bv = reinterpret_cast<const float4*>(bias)[lane];
    acc.x = fmaf(acc.x, dn, bv.x);
    acc.y = fmaf(acc.y, dn, bv.y);
    acc.z = fmaf(acc.z, dn, bv.z);
    acc.w = fmaf(acc.w, dn, bv.w);

    float s = acc.x + acc.y + acc.z + acc.w;
    float q = acc.x*acc.x + acc.y*acc.y + acc.z*acc.z + acc.w*acc.w;
    #pragma unroll
    for (int o = 16; o; o >>= 1) {
        s += __shfl_xor_sync(0xffffffffu, s, o);
        q += __shfl_xor_sync(0xffffffffu, q, o);
    }
    float mu  = s * (1.0f / 128.0f);
    float var = q * (1.0f / 128.0f) - mu * mu;
    float rs  = rsqrtf(var + EPSV);

    float4 gg = reinterpret_cast<const float4*>(gamma)[lane];
    float4 bt = reinterpret_cast<const float4*>(beta)[lane];
    float4 y;
    y.x = fmaxf(fmaf((acc.x - mu) * rs, gg.x, bt.x), 0.f);
    y.y = fmaxf(fmaf((acc.y - mu) * rs, gg.y, bt.y), 0.f);
    y.z = fmaxf(fmaf((acc.z - mu) * rs, gg.z, bt.z), 0.f);
    y.w = fmaxf(fmaf((acc.w - mu) * rs, gg.w, bt.w), 0.f);

    if (add_res) {
        float4 r = ld_h8(reinterpret_cast<const uint2*>(g_x), n, lane);
        y.x += r.x; y.y += r.y; y.z += r.z; y.w += r.w;
    }

    if (write_out) {
        stg_wt_v4(&dout[n * 128 + lane * 4], y);
        int b = batch_idx[n];
        red_add_v4(&g_pool[b * 128 + lane * 4], y);
        if (lane == 0) atomicAdd(&g_cnt[b], 1.0f);
    } else {
        uint2 u;
        __half2 h0 = __floats2half2_rn(y.x, y.y);
        __half2 h1 = __floats2half2_rn(y.z, y.w);
        u.x = *reinterpret_cast<uint32_t*>(&h0);
        u.y = *reinterpret_cast<uint32_t*>(&h1);
        reinterpret_cast<uint2*>(g_x)[n * 32 + lane] = u;
    }
}

__global__ void k_poolfin(float* __restrict__ dout) {
    int i = blockIdx.x * blockDim.x + threadIdx.x;
    if (i >= BB * HIDD) return;
    int b = i >> 7;
    float v = g_pool[i] / fmaxf(g_cnt[b], 1.0f);
    asm volatile("st.global.wt.f32 [%0], %1;"
                 :: "l"(&dout[NN * HIDD + i]), "f"(v) : "memory");
}

// ---------------- launch ------------------------------------------------------
extern "C" void kernel_launch(void* const* d_in, const int* in_sizes, int n_in,
                              void* d_out, int out_size)
{
    const float* nodes     = (const float*)d_in[0];
    const int*   edges     = (const int*)  d_in[1];
    const int*   batch_idx = (const int*)  d_in[3];
    const float* w_in      = (const float*)d_in[4];
    const float* b_in      = (const float*)d_in[5];
    const float* gcn_w     = (const float*)d_in[6];
    const float* gcn_b     = (const float*)d_in[7];
    const float* ln_g      = (const float*)d_in[8];
    const float* ln_b      = (const float*)d_in[9];
    float*       out       = (float*)d_out;

    const int* src = edges;
    const int* dst = edges + EE;

    static cudaStream_t s2 = nullptr;
    static cudaEvent_t ev_fork = nullptr, ev_mid = nullptr, ev_join = nullptr;
    static bool attr_set = false;
    if (!attr_set) {
        cudaFuncSetAttribute(k_gemm_mma,
                             cudaFuncAttributeMaxDynamicSharedMemorySize, GSMEM);
        cudaStreamCreateWithFlags(&s2, cudaStreamNonBlocking);
        cudaEventCreateWithFlags(&ev_fork, cudaEventDisableTiming);
        cudaEventCreateWithFlags(&ev_mid,  cudaEventDisableTiming);
        cudaEventCreateWithFlags(&ev_join, cudaEventDisableTiming);
        attr_set = true;
    }

    const int T = 256;
    const int INIT_N = (NN > BB * HIDD) ? NN : (BB * HIDD);
    const int FULL_GRID = (NN + 63) / 64;

    // fork: side stream does wconv + input-projection GEMM
    cudaEventRecord(ev_fork, 0);
    cudaStreamWaitEvent(s2, ev_fork, 0);
    k_wconv<<<(4 * HIDD * HIDD + T - 1) / T, T, 0, s2>>>(w_in, gcn_w);
    k_gemm_mma<<<FULL_GRID, T, GSMEM, s2>>>(nodes, b_in, 0, NN, 0, 0);

    // main stream: CSR prep up through scan_fin
    k_init <<<(INIT_N + T - 1) / T, T>>>();
    k_deg  <<<(EE + T * 4 - 1) / (T * 4), T>>>(dst);
    k_scan_blk<<<NPART, 1024>>>();
    k_scan_top<<<1, 32>>>();
    k_scan_fin<<<(NN + T - 1) / T, T>>>();
    cudaEventRecord(ev_mid, 0);

    // side stream: layer-0 GEMM overlaps k_fill
    cudaStreamWaitEvent(s2, ev_mid, 0);
    k_gemm_mma<<<FULL_GRID, T, GSMEM, s2>>>(nullptr, nullptr, 0, NN, 1, 1);
    cudaEventRecord(ev_join, s2);

    k_fill<<<(EE + T - 1) / T, T>>>(src, dst);
    cudaStreamWaitEvent(0, ev_join, 0);

    // ---- serial layer loop (single fp16 xw buffer) ----
    for (int i = 0; i < LLAY; i++) {
        if (i > 0)
            k_gemm_mma<<<FULL_GRID, T, GSMEM>>>(nullptr, nullptr, 0, NN, 1, i + 1);
        k_aggln<<<(NN * 32 + T - 1) / T, T>>>(gcn_b + i * HIDD,
                                              ln_g + i * HIDD, ln_b + i * HIDD,
                                              out, batch_idx,
                                              (i > 0) ? 1 : 0,
                                              (i == LLAY - 1) ? 1 : 0);
    }

    k_poolfin<<<(BB * HIDD + T - 1) / T, T>>>(out);
}